// round 6
// baseline (speedup 1.0000x reference)
#include <cuda_runtime.h>
#include <math.h>

// Equilibrium propagation, 256 serial iterations (R5 = R4 + staleness fix).
//
//  - 32 persistent CTAs x 256 threads; CTA c owns 128 output columns.
//  - W2 slice in smem twice (col-major & row-major, pitch 132 -> LDS.128,
//    4-phase conflict-free in both matvec directions).
//  - h state SHARDED: CTA c's warp w owns h-row r = 4c+w (state in lane 0).
//    Each CTA publishes 128 tagged partials {it, p} via st.relaxed.gpu.b64;
//    the owning warp does ONE coalesced 256B warp-load of
//    g_part[par][row][0..31], 5-shfl butterfly (fixed order -> deterministic),
//    lane0 Adam, publishes clamped r_h[row] as one tagged word.
//  - o-side threads (128..255) poll one g_rh word each (coalesced), stash to
//    smem, o-only named barrier, pass1 + o Adam.
//  - CRITICAL ordering: s_ro holds the OLD clamp(o) when pass2 reads it
//    (reference computes g_h from r_o of the previous state). The o-side
//    therefore writes s_ro[j] BEFORE applying its Adam update.
//  - No fences anywhere; tags + parity bound skew. Safety of the single
//    syncthreads: o-side at iter it+1 cannot pass its g_rh poll until every
//    h-warp published iter it, which happens after that warp's s_ro reads.

#define G      32
#define T      256
#define HID    128
#define OUT    4096
#define COLS   128            // OUT / G
#define IN     65536
#define XCTAS  256
#define XROWS  (IN / XCTAS)   // 256
#define PITCH  132            // 528 B: float4-aligned, 4-phase conflict-free

__device__ float g_xpart[XCTAS * HID];
__device__ unsigned long long g_part[2][HID][G];  // [parity][row][cta] {tag,val}
__device__ unsigned long long g_rh[2][HID];       // [parity][row]      {tag,val}

__device__ __forceinline__ unsigned long long ldx(const unsigned long long* p) {
    unsigned long long v;
    asm volatile("ld.relaxed.gpu.global.b64 %0, [%1];" : "=l"(v) : "l"(p) : "memory");
    return v;
}
__device__ __forceinline__ void stx(unsigned long long* p, unsigned long long v) {
    asm volatile("st.relaxed.gpu.global.b64 [%0], %1;" :: "l"(p), "l"(v) : "memory");
}
__device__ __forceinline__ float clampf(float v) {
    return fminf(fmaxf(v, 0.f), 1.f);
}
__device__ __forceinline__ unsigned long long pack(int tag, float v) {
    return ((unsigned long long)(unsigned)tag << 32) |
           (unsigned long long)__float_as_uint(v);
}

// ---------------------------------------------------------------------------
// Kernel A: xW1 partials (one-time, HBM-bound) + reset of all exchange tags
// so graph replays never observe stale {tag==it} matches.
// ---------------------------------------------------------------------------
__global__ __launch_bounds__(256) void xw1_kernel(
    const float* __restrict__ x, const float* __restrict__ W1)
{
    __shared__ float tmp[HID];
    int t   = threadIdx.x;
    int col = t & (HID - 1);
    int rp  = t >> 7;
    int base = blockIdx.x * XROWS + rp * (XROWS / 2);

    float acc = 0.f;
#pragma unroll 4
    for (int k = 0; k < XROWS / 2; ++k) {
        int i = base + k;
        acc += clampf(x[i]) * W1[(size_t)i * HID + col];
    }
    if (rp == 1) tmp[col] = acc;
    __syncthreads();
    if (rp == 0) g_xpart[blockIdx.x * HID + col] = acc + tmp[col];

    // reset tags: g_part (2*128*32 = 8192 words) + g_rh (256 words)
    int gid = blockIdx.x * 256 + t;
    if (gid < 2 * HID * G)
        ((unsigned long long*)g_part)[gid] = 0ull;
    else if (gid < 2 * HID * G + 2 * HID)
        ((unsigned long long*)g_rh)[gid - 2 * HID * G] = 0ull;
}

// ---------------------------------------------------------------------------
// Kernel B: persistent iteration kernel.
// ---------------------------------------------------------------------------
extern __shared__ float smem_dyn[];

__global__ __launch_bounds__(T, 1) void eqprop_kernel(
    const float* __restrict__ W2,
    const float* __restrict__ b_h,
    const float* __restrict__ b_out,
    const float* __restrict__ h0,
    const float* __restrict__ o0,
    const int*   __restrict__ n_it_p,
    const float* __restrict__ eps_p,
    float*       __restrict__ out)
{
    float* W2c = smem_dyn;                     // [COLS][PITCH] (col-major)
    float* W2r = smem_dyn + COLS * PITCH;      // [HID][PITCH]  (row-major)
    __shared__ __align__(16) float s_rh[HID];
    __shared__ __align__(16) float s_ro[COLS];

    const int t    = threadIdx.x;
    const int c    = blockIdx.x;
    const int lane = t & 31;
    const int warp = t >> 5;

    int n_it = *n_it_p;
    if (!(n_it > 0 && n_it < (1 << 20))) {
        n_it = (int)__int_as_float(n_it);
        if (!(n_it > 0 && n_it < (1 << 20))) n_it = 256;
    }
    const float eps = *eps_p;

    // --- W2 slice -> both smem layouts (one-time, coalesced LDG) ---
    for (int idx = t; idx < HID * COLS; idx += T) {
        int i = idx >> 7;            // hidden row
        int j = idx & (COLS - 1);    // local column
        float w = W2[(size_t)i * OUT + (size_t)c * COLS + j];
        W2c[j * PITCH + i] = w;
        W2r[i * PITCH + j] = w;
    }

    // --- sharded h state: warp w (w<4) of CTA c owns row = 4c + w, lane 0 ---
    const int row = c * 4 + warp;              // valid for t < 128
    float hreg = 0.f, mh = 0.f, vh = 0.f, bh = 0.f, hW = 0.f;
    float oreg = 0.f, mo = 0.f, vo = 0.f, bo = 0.f;
    if (t < HID) {
        // warp-cooperative xW1[row] reduction (fixed order -> deterministic)
        float s = 0.f;
#pragma unroll
        for (int q = 0; q < XCTAS / 32; ++q)
            s += g_xpart[(lane + 32 * q) * HID + row];
#pragma unroll
        for (int m = 16; m; m >>= 1) s += __shfl_xor_sync(0xFFFFFFFFu, s, m);
        if (lane == 0) {
            hW   = s;
            hreg = h0[row];
            bh   = b_h[row];
        }
    } else {
        int j = t - HID;
        oreg = o0[c * COLS + j];
        bo   = b_out[c * COLS + j];
    }
    __syncthreads();   // smem W2 ready

    float pw1 = 1.f, pw2 = 1.f;

    for (int it = 1; it <= n_it; ++it) {
        const int par = it & 1;
        pw1 *= 0.9f;
        pw2 *= 0.999f;
        const float ic1 = 1.f / (1.f - pw1);
        const float ic2 = 1.f / (1.f - pw2);

        if (t >= HID) {
            const int j = t - HID;
            // ---- gather r_h(it-1): one tagged word per thread, coalesced ----
            if (it == 1) {
                s_rh[j] = clampf(h0[j]);
            } else {
                const unsigned long long* p = &g_rh[par ^ 1][j];
                unsigned long long v = ldx(p);
                while ((int)(v >> 32) != it - 1) v = ldx(p);
                s_rh[j] = __uint_as_float((unsigned)v);
            }
            asm volatile("bar.sync 1, 128;" ::: "memory");   // o-side only

            // ---- pass 1: y_j = sum_i r_h[i] * W2[i,j] ----
            const float4* wc  = (const float4*)(W2c + j * PITCH);
            const float4* rh4 = (const float4*)s_rh;
            float4 a = make_float4(0.f, 0.f, 0.f, 0.f);
#pragma unroll
            for (int q = 0; q < HID / 4; ++q) {
                float4 w = wc[q], r = rh4[q];
                a.x += w.x * r.x; a.y += w.y * r.y;
                a.z += w.z * r.z; a.w += w.w * r.w;
            }
            float y = (a.x + a.y) + (a.z + a.w);

            // ---- o Adam: s_ro gets the OLD clamp (pass2 needs r_o(it-1)) ----
            float ro   = clampf(oreg);
            s_ro[j] = ro;                       // OLD r_o, before the update
            float mask = (oreg >= 0.f && oreg <= 1.f) ? 1.f : 0.f;
            float g    = mask * (ro - bo - y);
            mo = 0.9f  * mo + 0.1f  * g;
            vo = 0.999f * vo + 0.001f * g * g;
            oreg -= eps * (mo * ic1) / (sqrtf(vo * ic2) + 1e-8f);
        }
        __syncthreads();   // s_ro (OLD r_o) ready for h-side

        if (t < HID) {
            // ---- pass 2: p_t = sum_j W2[t,j] * r_o_old[j] (this CTA's cols) ----
            const float4* wr  = (const float4*)(W2r + t * PITCH);
            const float4* ro4 = (const float4*)s_ro;
            float4 a = make_float4(0.f, 0.f, 0.f, 0.f);
#pragma unroll
            for (int q = 0; q < COLS / 4; ++q) {
                float4 w = wr[q], r = ro4[q];
                a.x += w.x * r.x; a.y += w.y * r.y;
                a.z += w.z * r.z; a.w += w.w * r.w;
            }
            float p = (a.x + a.y) + (a.z + a.w);
            stx(&g_part[par][t][c], pack(it, p));       // publish partial

            // ---- reduce owned row: coalesced 256B warp-load + butterfly ----
            const unsigned long long* pp = &g_part[par][row][lane];
            unsigned long long v = ldx(pp);
            while ((int)(v >> 32) != it) v = ldx(pp);
            float s = __uint_as_float((unsigned)v);
#pragma unroll
            for (int m = 16; m; m >>= 1) s += __shfl_xor_sync(0xFFFFFFFFu, s, m);

            if (lane == 0) {
                // ---- h Adam for owned row; publish clamped r_h ----
                float rh   = clampf(hreg);
                float mask = (hreg >= 0.f && hreg <= 1.f) ? 1.f : 0.f;
                float g    = mask * (rh - bh - hW - s);
                mh = 0.9f  * mh + 0.1f  * g;
                vh = 0.999f * vh + 0.001f * g * g;
                hreg -= eps * (mh * ic1) / (sqrtf(vh * ic2) + 1e-8f);
                stx(&g_rh[par][row], pack(it, clampf(hreg)));
            }
        }
    }

    if (t >= HID)
        out[c * COLS + (t - HID)] = oreg;
}

// ---------------------------------------------------------------------------
extern "C" void kernel_launch(void* const* d_in, const int* in_sizes, int n_in,
                              void* d_out, int out_size)
{
    const float* x     = (const float*)d_in[0];
    const float* W1    = (const float*)d_in[1];
    const float* W2    = (const float*)d_in[2];
    // d_in[3] = b_in (unused by the reference math)
    const float* b_h   = (const float*)d_in[4];
    const float* b_out = (const float*)d_in[5];
    const float* h0    = (const float*)d_in[6];
    const float* o0    = (const float*)d_in[7];
    const int*   n_it  = (const int*)d_in[8];
    const float* eps   = (const float*)d_in[9];
    float* out = (float*)d_out;

    static int configured = 0;
    const int smem_bytes = 2 * HID * PITCH * sizeof(float);   // 135,168 B
    if (!configured) {
        cudaFuncSetAttribute(eqprop_kernel,
                             cudaFuncAttributeMaxDynamicSharedMemorySize,
                             smem_bytes);
        configured = 1;
    }

    xw1_kernel<<<XCTAS, 256>>>(x, W1);
    eqprop_kernel<<<G, T, smem_bytes>>>(W2, b_h, b_out, h0, o0, n_it, eps, out);
}